// round 2
// baseline (speedup 1.0000x reference)
#include <cuda_runtime.h>

// SuperchargingBKT: BKT + multidim IRT forward scan.
// B=8192 rows, T=512 steps. One thread per row, software-pipelined in chunks
// of U=8 steps: gathers for chunk c+1 are in flight while chunk c's serial
// recurrence executes.
//
// Inputs (metadata order):
//  0 pL0_logit [K]  f32      6 sigma  [P]        f32
//  1 pT_logit  [K]  f32      7 student_ability [S,4] f32
//  2 pF_logit  [K]  f32      8 observations [B,T] i32
//  3 pG_logit  [K]  f32      9 kc_ids       [B,T] i32
//  4 pS_logit  [K]  f32     10 problem_ids  [B,T] i32
//  5 omega     [P]  f32     11 student_ids  [B,T] i32
// Output: p_correct [B,T] f32

constexpr int T_LEN = 512;
constexpr int U     = 8;            // pipeline chunk (steps)
constexpr int NCH   = T_LEN / U;
constexpr float EPSF = 1e-8f;

__device__ __forceinline__ float sigmoidf(float x) {
    return __fdividef(1.0f, 1.0f + __expf(-x));
}

struct Raw {
    int    ob[U];
    float  lT[U], lF[U], lG[U], lS[U], om[U], sg[U];
    float4 th[U];
};

__device__ __forceinline__ void load_raw(
    Raw& r, int off,
    const float* __restrict__ pT_logit, const float* __restrict__ pF_logit,
    const float* __restrict__ pG_logit, const float* __restrict__ pS_logit,
    const float* __restrict__ omega,    const float* __restrict__ sigma,
    const float4* __restrict__ ability,
    const int* __restrict__ obs, const int* __restrict__ kc,
    const int* __restrict__ pid, const int* __restrict__ sid)
{
    // vectorized index loads (16B aligned: off is a multiple of 8, base of each
    // row is a multiple of 512)
    int4 kv0 = *reinterpret_cast<const int4*>(kc  + off);
    int4 kv1 = *reinterpret_cast<const int4*>(kc  + off + 4);
    int4 pv0 = *reinterpret_cast<const int4*>(pid + off);
    int4 pv1 = *reinterpret_cast<const int4*>(pid + off + 4);
    int4 sv0 = *reinterpret_cast<const int4*>(sid + off);
    int4 sv1 = *reinterpret_cast<const int4*>(sid + off + 4);
    int4 ov0 = *reinterpret_cast<const int4*>(obs + off);
    int4 ov1 = *reinterpret_cast<const int4*>(obs + off + 4);

    int kcs[U] = {kv0.x, kv0.y, kv0.z, kv0.w, kv1.x, kv1.y, kv1.z, kv1.w};
    int ps[U]  = {pv0.x, pv0.y, pv0.z, pv0.w, pv1.x, pv1.y, pv1.z, pv1.w};
    int ss[U]  = {sv0.x, sv0.y, sv0.z, sv0.w, sv1.x, sv1.y, sv1.z, sv1.w};
    int os[U]  = {ov0.x, ov0.y, ov0.z, ov0.w, ov1.x, ov1.y, ov1.z, ov1.w};

#pragma unroll
    for (int i = 0; i < U; ++i) {
        r.ob[i] = os[i];
        r.lT[i] = __ldg(pT_logit + kcs[i]);
        r.lF[i] = __ldg(pF_logit + kcs[i]);
        r.lG[i] = __ldg(pG_logit + kcs[i]);
        r.lS[i] = __ldg(pS_logit + kcs[i]);
        r.om[i] = __ldg(omega + ps[i]);
        r.sg[i] = __ldg(sigma + ps[i]);
        r.th[i] = __ldg(ability + ss[i]);
    }
}

__global__ void __launch_bounds__(64, 1)
bkt_scan_kernel(
    const float* __restrict__ pL0_logit,
    const float* __restrict__ pT_logit,
    const float* __restrict__ pF_logit,
    const float* __restrict__ pG_logit,
    const float* __restrict__ pS_logit,
    const float* __restrict__ omega,
    const float* __restrict__ sigma,
    const float4* __restrict__ ability,
    const int*  __restrict__ obs,
    const int*  __restrict__ kc,
    const int*  __restrict__ pid,
    const int*  __restrict__ sid,
    float* __restrict__ out,
    int B)
{
    int b = blockIdx.x * blockDim.x + threadIdx.x;
    if (b >= B) return;
    const int base = b * T_LEN;

    // initial state from pL0 at first KC
    float pL0 = sigmoidf(__ldg(pL0_logit + __ldg(kc + base)));
    float hm = pL0;          // mastered
    float hu = 1.0f - pL0;   // unmastered

    Raw raw;
    load_raw(raw, base, pT_logit, pF_logit, pG_logit, pS_logit,
             omega, sigma, ability, obs, kc, pid, sid);

    float c1[U], c2[U], c3[U], c4[U], c5[U], c6[U];

    for (int c = 0; c < NCH; ++c) {
        // ---- stage 1: form coefficients from the already-landed gathers ----
#pragma unroll
        for (int i = 0; i < U; ++i) {
            float4 th = raw.th[i];
            float pT = sigmoidf(raw.lT[i] + th.x);
            float pF = sigmoidf(raw.lF[i] - th.y);
            float pG = sigmoidf(raw.lG[i] + raw.om[i] + th.z);
            float pS = sigmoidf(raw.lS[i] + raw.sg[i] - th.w);
            bool o = (raw.ob[i] != 0);
            float pom = o ? (1.0f - pS) : pS;   // P(y | mastered)
            float pou = o ? pG : (1.0f - pG);   // P(y | unmastered)
            c1[i] = (1.0f - pF) * pom;          // nm <- c1*hm + c2*hu
            c2[i] = pT * pou;
            c3[i] = pF * pom;                   // nu <- c3*hm + c4*hu
            c4[i] = (1.0f - pT) * pou;
            c5[i] = 1.0f - pS;                  // pc = c5*nm + c6*nu (normalized)
            c6[i] = pG;
        }

        // ---- stage 2: issue next chunk's loads (latency hidden by stage 3) ----
        if (c + 1 < NCH) {
            load_raw(raw, base + (c + 1) * U,
                     pT_logit, pF_logit, pG_logit, pS_logit,
                     omega, sigma, ability, obs, kc, pid, sid);
        }

        // ---- stage 3: serial recurrence for this chunk ----
        float* o = out + base + c * U;
#pragma unroll
        for (int i = 0; i < U; ++i) {
            float nm = fmaf(c1[i], hm, c2[i] * hu);
            float nu = fmaf(c3[i], hm, c4[i] * hu);
            float z  = nm + nu + EPSF;
            float r  = __fdividef(1.0f, z);
            hm = nm * r;
            hu = nu * r;
            o[i] = fmaf(c5[i], hm, c6[i] * hu);
        }
    }
}

extern "C" void kernel_launch(void* const* d_in, const int* in_sizes, int n_in,
                              void* d_out, int out_size) {
    const float* pL0 = (const float*)d_in[0];
    const float* pT  = (const float*)d_in[1];
    const float* pF  = (const float*)d_in[2];
    const float* pG  = (const float*)d_in[3];
    const float* pS  = (const float*)d_in[4];
    const float* om  = (const float*)d_in[5];
    const float* sg  = (const float*)d_in[6];
    const float4* ab = (const float4*)d_in[7];
    const int* obs = (const int*)d_in[8];
    const int* kc  = (const int*)d_in[9];
    const int* pid = (const int*)d_in[10];
    const int* sid = (const int*)d_in[11];
    float* out = (float*)d_out;

    int B = in_sizes[8] / T_LEN;   // 8192
    dim3 block(64);
    dim3 grid((B + block.x - 1) / block.x);
    bkt_scan_kernel<<<grid, block>>>(pL0, pT, pF, pG, pS, om, sg, ab,
                                     obs, kc, pid, sid, out, B);
}

// round 3
// speedup vs baseline: 1.8099x; 1.8099x over previous
#include <cuda_runtime.h>

// SuperchargingBKT — warp-per-row parallel scan formulation.
//
// The per-step recurrence (with EPS dropped; effect ~1e-7/step, tol 1e-3):
//   (hu,hm)_t  ∝  M_t (hu,hm)_{t-1},   M_t = [[c4,c3],[c2,c1]]
//   pc_t = (c5*hm + c6*hu) after normalization
// is a projective linear 2x2 recurrence -> associative matrix scan.
//
// Layout: 1 warp per row (B=8192 rows). Each lane owns SEG=16 consecutive
// steps. Pass 1: gather + sigmoids + per-lane segment matrix product
// (coefficients kept in registers). Warp shuffle scan of 2x2 matrices gives
// each lane its exclusive prefix; pass 2 replays the 16 steps from the known
// start state and emits p_correct.
//
// Inputs (metadata order):
//  0 pL0_logit [K] f32   4 pS_logit [K] f32    8 observations [B,T] i32
//  1 pT_logit  [K] f32   5 omega    [P] f32    9 kc_ids       [B,T] i32
//  2 pF_logit  [K] f32   6 sigma    [P] f32   10 problem_ids  [B,T] i32
//  3 pG_logit  [K] f32   7 ability  [S,4] f32 11 student_ids  [B,T] i32
// Output: p_correct [B,T] f32

constexpr int T_LEN = 512;
constexpr int SEG   = 16;                 // steps per lane (32 lanes * 16 = 512)
constexpr int ROWS_PER_BLOCK = 8;
constexpr int THREADS = ROWS_PER_BLOCK * 32;

__device__ __forceinline__ float sigmoidf(float x) {
    return __fdividef(1.0f, 1.0f + __expf(-x));
}

__global__ void __launch_bounds__(THREADS, 2)   // cap at 128 regs -> 16 warps/SM
bkt_warp_scan(
    const float* __restrict__ pL0_logit,
    const float* __restrict__ pT_logit,
    const float* __restrict__ pF_logit,
    const float* __restrict__ pG_logit,
    const float* __restrict__ pS_logit,
    const float* __restrict__ omega,
    const float* __restrict__ sigma,
    const float4* __restrict__ ability,
    const int*  __restrict__ obs,
    const int*  __restrict__ kc,
    const int*  __restrict__ pid,
    const int*  __restrict__ sid,
    float* __restrict__ out,
    int B)
{
    const int warp = (blockIdx.x * blockDim.x + threadIdx.x) >> 5;
    const int lane = threadIdx.x & 31;
    if (warp >= B) return;

    const int base = warp * T_LEN;
    const int s0   = base + lane * SEG;    // this lane's first step

    float C1[SEG], C2[SEG], C3[SEG], C4[SEG];
    unsigned obits = 0;

    // A maps this lane's segment-start state (hu,hm) -> state after processed
    // steps. Row0 -> hu', Row1 -> hm'.
    float a00 = 1.f, a01 = 0.f, a10 = 0.f, a11 = 1.f;

    // ---------------- pass 1: coefficients + segment matrix product --------
#pragma unroll
    for (int q = 0; q < SEG / 4; ++q) {
        const int o4i = s0 + 4 * q;
        int4 kv = *reinterpret_cast<const int4*>(kc  + o4i);
        int4 pv = *reinterpret_cast<const int4*>(pid + o4i);
        int4 sv = *reinterpret_cast<const int4*>(sid + o4i);
        int4 ov = *reinterpret_cast<const int4*>(obs + o4i);
        int kk[4] = {kv.x, kv.y, kv.z, kv.w};
        int pp[4] = {pv.x, pv.y, pv.z, pv.w};
        int ssx[4]= {sv.x, sv.y, sv.z, sv.w};
        int oo[4] = {ov.x, ov.y, ov.z, ov.w};

#pragma unroll
        for (int j = 0; j < 4; ++j) {
            const int i = 4 * q + j;
            float4 th = __ldg(ability + ssx[j]);
            float pT = sigmoidf(__ldg(pT_logit + kk[j]) + th.x);
            float pF = sigmoidf(__ldg(pF_logit + kk[j]) - th.y);
            float pG = sigmoidf(__ldg(pG_logit + kk[j]) + __ldg(omega + pp[j]) + th.z);
            float pS = sigmoidf(__ldg(pS_logit + kk[j]) + __ldg(sigma + pp[j]) - th.w);
            bool o = (oo[j] != 0);
            float pom = o ? (1.0f - pS) : pS;      // P(y | mastered)
            float pou = o ? pG : (1.0f - pG);      // P(y | unmastered)
            float c1 = (1.0f - pF) * pom;
            float c2 = pT * pou;
            float c3 = pF * pom;
            float c4 = (1.0f - pT) * pou;
            C1[i] = c1; C2[i] = c2; C3[i] = c3; C4[i] = c4;
            obits |= (o ? 1u : 0u) << i;

            // A = M * A,  M = [[c4,c3],[c2,c1]]
            float n00 = fmaf(c4, a00, c3 * a10);
            float n01 = fmaf(c4, a01, c3 * a11);
            float n10 = fmaf(c2, a00, c1 * a10);
            float n11 = fmaf(c2, a01, c1 * a11);
            a00 = n00; a01 = n01; a10 = n10; a11 = n11;
        }
        // periodic normalization (projective: scale is irrelevant)
        float r = __fdividef(1.0f, a00 + a01 + a10 + a11);
        a00 *= r; a01 *= r; a10 *= r; a11 *= r;
    }

    // ------------- inclusive warp scan of segment matrices -----------------
    // lane l ends holding  P_l * P_{l-1} * ... * P_0
#pragma unroll
    for (int d = 1; d < 32; d <<= 1) {
        float b00 = __shfl_up_sync(0xFFFFFFFFu, a00, d);
        float b01 = __shfl_up_sync(0xFFFFFFFFu, a01, d);
        float b10 = __shfl_up_sync(0xFFFFFFFFu, a10, d);
        float b11 = __shfl_up_sync(0xFFFFFFFFu, a11, d);
        if (lane >= d) {
            float n00 = fmaf(a00, b00, a01 * b10);   // mine(later) * other(earlier)
            float n01 = fmaf(a00, b01, a01 * b11);
            float n10 = fmaf(a10, b00, a11 * b10);
            float n11 = fmaf(a10, b01, a11 * b11);
            float r = __fdividef(1.0f, n00 + n01 + n10 + n11);
            a00 = n00 * r; a01 = n01 * r; a10 = n10 * r; a11 = n11 * r;
        }
    }

    // exclusive prefix: lane l needs product over steps [0, l*SEG)
    float e00 = __shfl_up_sync(0xFFFFFFFFu, a00, 1);
    float e01 = __shfl_up_sync(0xFFFFFFFFu, a01, 1);
    float e10 = __shfl_up_sync(0xFFFFFFFFu, a10, 1);
    float e11 = __shfl_up_sync(0xFFFFFFFFu, a11, 1);
    if (lane == 0) { e00 = 1.f; e01 = 0.f; e10 = 0.f; e11 = 1.f; }

    // initial state from pL0 at first KC (uniform broadcast load)
    float pL0 = sigmoidf(__ldg(pL0_logit + __ldg(kc + base)));
    float hu0 = 1.0f - pL0;
    float hm0 = pL0;
    float hu = fmaf(e00, hu0, e01 * hm0);
    float hm = fmaf(e10, hu0, e11 * hm0);
    float rs = __fdividef(1.0f, hu + hm);
    hu *= rs; hm *= rs;

    // ---------------- pass 2: replay segment, emit p_correct ---------------
    float* op = out + s0;
#pragma unroll
    for (int q = 0; q < SEG / 4; ++q) {
        float4 res;
        float* r4 = reinterpret_cast<float*>(&res);
#pragma unroll
        for (int j = 0; j < 4; ++j) {
            const int i = 4 * q + j;
            float nm = fmaf(C1[i], hm, C2[i] * hu);
            float nu = fmaf(C3[i], hm, C4[i] * hu);
            float r  = __fdividef(1.0f, nm + nu);
            hm = nm * r;
            hu = nu * r;
            bool o = (obits >> i) & 1u;
            float pom = C1[i] + C3[i];             // = 1-pS if o else pS
            float pou = C2[i] + C4[i];             // = pG   if o else 1-pG
            float c5 = o ? pom : (1.0f - pom);     // 1-pS
            float c6 = o ? pou : (1.0f - pou);     // pG
            r4[j] = fmaf(c5, hm, c6 * hu);
        }
        *reinterpret_cast<float4*>(op + 4 * q) = res;
    }
}

extern "C" void kernel_launch(void* const* d_in, const int* in_sizes, int n_in,
                              void* d_out, int out_size) {
    const float* pL0 = (const float*)d_in[0];
    const float* pT  = (const float*)d_in[1];
    const float* pF  = (const float*)d_in[2];
    const float* pG  = (const float*)d_in[3];
    const float* pS  = (const float*)d_in[4];
    const float* om  = (const float*)d_in[5];
    const float* sg  = (const float*)d_in[6];
    const float4* ab = (const float4*)d_in[7];
    const int* obs = (const int*)d_in[8];
    const int* kc  = (const int*)d_in[9];
    const int* pid = (const int*)d_in[10];
    const int* sid = (const int*)d_in[11];
    float* out = (float*)d_out;

    int B = in_sizes[8] / T_LEN;                  // 8192 rows
    int warps_per_block = THREADS / 32;
    int grid = (B + warps_per_block - 1) / warps_per_block;
    bkt_warp_scan<<<grid, THREADS>>>(pL0, pT, pF, pG, pS, om, sg, ab,
                                     obs, kc, pid, sid, out, B);
}

// round 4
// speedup vs baseline: 1.8814x; 1.0395x over previous
#include <cuda_runtime.h>

// SuperchargingBKT — warp-per-row 2x2 projective matrix scan, round 3.
//
// R3 changes vs R2:
//  * pre-kernel packs (pT,pF,pG,pS)_logit -> float4 table and (omega,sigma)
//    -> float2 table in __device__ scratch: 6 scalar gathers/step -> 2 vector
//    gathers/step (~2.2x fewer L1 wavefronts; L1 was 64% busy).
//  * replay coefficients C1..C3 cached in shared memory (48KB/CTA,
//    [step][k][tid], conflict-free, thread-private -> no syncs); C4 in regs.
//    With __launch_bounds__(256,3) => 24 warps/SM instead of 16.
//  * segment-matrix renormalization every 8 steps instead of 4.
//
// Inputs (metadata order):
//  0 pL0_logit [K] f32   4 pS_logit [K] f32    8 observations [B,T] i32
//  1 pT_logit  [K] f32   5 omega    [P] f32    9 kc_ids       [B,T] i32
//  2 pF_logit  [K] f32   6 sigma    [P] f32   10 problem_ids  [B,T] i32
//  3 pG_logit  [K] f32   7 ability  [S,4] f32 11 student_ids  [B,T] i32
// Output: p_correct [B,T] f32

constexpr int T_LEN = 512;
constexpr int SEG   = 16;                 // steps per lane (32 lanes * 16 = 512)
constexpr int THREADS = 256;
constexpr int K_CAP = 1024;               // K = 1000
constexpr int P_CAP = 50048;              // P = 50000

__device__ float4 g_kcpack[K_CAP];        // (pT,pF,pG,pS) logits per KC
__device__ float2 g_pspack[P_CAP];        // (omega,sigma) per problem

__device__ __forceinline__ float sigmoidf(float x) {
    return __fdividef(1.0f, 1.0f + __expf(-x));
}

__global__ void pack_tables(
    const float* __restrict__ pT_logit, const float* __restrict__ pF_logit,
    const float* __restrict__ pG_logit, const float* __restrict__ pS_logit,
    const float* __restrict__ omega,    const float* __restrict__ sigma,
    int K, int P)
{
    int i = blockIdx.x * blockDim.x + threadIdx.x;
    if (i < K) {
        g_kcpack[i] = make_float4(pT_logit[i], pF_logit[i], pG_logit[i], pS_logit[i]);
    }
    if (i < P) {
        g_pspack[i] = make_float2(omega[i], sigma[i]);
    }
}

__global__ void __launch_bounds__(THREADS, 3)
bkt_warp_scan(
    const float* __restrict__ pL0_logit,
    const float4* __restrict__ ability,
    const int*  __restrict__ obs,
    const int*  __restrict__ kc,
    const int*  __restrict__ pid,
    const int*  __restrict__ sid,
    float* __restrict__ out,
    int B)
{
    // 48KB replay cache: c1,c2,c3 per (step, thread). Thread-private slots.
    __shared__ float sC[SEG][3][THREADS];

    const int warp = (blockIdx.x * blockDim.x + threadIdx.x) >> 5;
    const int lane = threadIdx.x & 31;
    const int tid  = threadIdx.x;
    if (warp >= B) return;

    const int base = warp * T_LEN;
    const int s0   = base + lane * SEG;    // this lane's first step

    float C4[SEG];
    unsigned obits = 0;

    // A maps segment-start state (hu,hm) -> state after processed steps.
    float a00 = 1.f, a01 = 0.f, a10 = 0.f, a11 = 1.f;

    // ---------------- pass 1: coefficients + segment matrix product --------
#pragma unroll
    for (int q = 0; q < SEG / 4; ++q) {
        const int o4i = s0 + 4 * q;
        int4 kv = *reinterpret_cast<const int4*>(kc  + o4i);
        int4 pv = *reinterpret_cast<const int4*>(pid + o4i);
        int4 sv = *reinterpret_cast<const int4*>(sid + o4i);
        int4 ov = *reinterpret_cast<const int4*>(obs + o4i);
        int kk[4] = {kv.x, kv.y, kv.z, kv.w};
        int pp[4] = {pv.x, pv.y, pv.z, pv.w};
        int ssx[4]= {sv.x, sv.y, sv.z, sv.w};
        int oo[4] = {ov.x, ov.y, ov.z, ov.w};

#pragma unroll
        for (int j = 0; j < 4; ++j) {
            const int i = 4 * q + j;
            float4 th = __ldg(ability + ssx[j]);
            float4 kcp = g_kcpack[kk[j]];
            float2 psp = g_pspack[pp[j]];
            float pT = sigmoidf(kcp.x + th.x);
            float pF = sigmoidf(kcp.y - th.y);
            float pG = sigmoidf(kcp.z + psp.x + th.z);
            float pS = sigmoidf(kcp.w + psp.y - th.w);
            bool o = (oo[j] != 0);
            float pom = o ? (1.0f - pS) : pS;      // P(y | mastered)
            float pou = o ? pG : (1.0f - pG);      // P(y | unmastered)
            float c1 = (1.0f - pF) * pom;
            float c2 = pT * pou;
            float c3 = pF * pom;
            float c4 = (1.0f - pT) * pou;
            sC[i][0][tid] = c1;
            sC[i][1][tid] = c2;
            sC[i][2][tid] = c3;
            C4[i] = c4;
            obits |= (o ? 1u : 0u) << i;

            // A = M * A,  M = [[c4,c3],[c2,c1]]
            float n00 = fmaf(c4, a00, c3 * a10);
            float n01 = fmaf(c4, a01, c3 * a11);
            float n10 = fmaf(c2, a00, c1 * a10);
            float n11 = fmaf(c2, a01, c1 * a11);
            a00 = n00; a01 = n01; a10 = n10; a11 = n11;
        }
        if (q & 1) {
            // normalize every 8 steps (projective scale is irrelevant)
            float r = __fdividef(1.0f, a00 + a01 + a10 + a11);
            a00 *= r; a01 *= r; a10 *= r; a11 *= r;
        }
    }

    // ------------- inclusive warp scan of segment matrices -----------------
#pragma unroll
    for (int d = 1; d < 32; d <<= 1) {
        float b00 = __shfl_up_sync(0xFFFFFFFFu, a00, d);
        float b01 = __shfl_up_sync(0xFFFFFFFFu, a01, d);
        float b10 = __shfl_up_sync(0xFFFFFFFFu, a10, d);
        float b11 = __shfl_up_sync(0xFFFFFFFFu, a11, d);
        if (lane >= d) {
            float n00 = fmaf(a00, b00, a01 * b10);   // mine(later) * other(earlier)
            float n01 = fmaf(a00, b01, a01 * b11);
            float n10 = fmaf(a10, b00, a11 * b10);
            float n11 = fmaf(a10, b01, a11 * b11);
            float r = __fdividef(1.0f, n00 + n01 + n10 + n11);
            a00 = n00 * r; a01 = n01 * r; a10 = n10 * r; a11 = n11 * r;
        }
    }

    // exclusive prefix
    float e00 = __shfl_up_sync(0xFFFFFFFFu, a00, 1);
    float e01 = __shfl_up_sync(0xFFFFFFFFu, a01, 1);
    float e10 = __shfl_up_sync(0xFFFFFFFFu, a10, 1);
    float e11 = __shfl_up_sync(0xFFFFFFFFu, a11, 1);
    if (lane == 0) { e00 = 1.f; e01 = 0.f; e10 = 0.f; e11 = 1.f; }

    // initial state from pL0 at first KC (uniform broadcast load)
    float pL0 = sigmoidf(__ldg(pL0_logit + __ldg(kc + base)));
    float hu0 = 1.0f - pL0;
    float hm0 = pL0;
    float hu = fmaf(e00, hu0, e01 * hm0);
    float hm = fmaf(e10, hu0, e11 * hm0);
    float rs = __fdividef(1.0f, hu + hm);
    hu *= rs; hm *= rs;

    // ---------------- pass 2: replay segment, emit p_correct ---------------
    float* op = out + s0;
#pragma unroll
    for (int q = 0; q < SEG / 4; ++q) {
        float4 res;
        float* r4 = reinterpret_cast<float*>(&res);
#pragma unroll
        for (int j = 0; j < 4; ++j) {
            const int i = 4 * q + j;
            float c1 = sC[i][0][tid];
            float c2 = sC[i][1][tid];
            float c3 = sC[i][2][tid];
            float c4 = C4[i];
            float nm = fmaf(c1, hm, c2 * hu);
            float nu = fmaf(c3, hm, c4 * hu);
            float r  = __fdividef(1.0f, nm + nu);
            hm = nm * r;
            hu = nu * r;
            bool o = (obits >> i) & 1u;
            float pom = c1 + c3;                   // = 1-pS if o else pS
            float pou = c2 + c4;                   // = pG   if o else 1-pG
            float c5 = o ? pom : (1.0f - pom);     // 1-pS
            float c6 = o ? pou : (1.0f - pou);     // pG
            r4[j] = fmaf(c5, hm, c6 * hu);
        }
        *reinterpret_cast<float4*>(op + 4 * q) = res;
    }
}

extern "C" void kernel_launch(void* const* d_in, const int* in_sizes, int n_in,
                              void* d_out, int out_size) {
    const float* pL0 = (const float*)d_in[0];
    const float* pT  = (const float*)d_in[1];
    const float* pF  = (const float*)d_in[2];
    const float* pG  = (const float*)d_in[3];
    const float* pS  = (const float*)d_in[4];
    const float* om  = (const float*)d_in[5];
    const float* sg  = (const float*)d_in[6];
    const float4* ab = (const float4*)d_in[7];
    const int* obs = (const int*)d_in[8];
    const int* kc  = (const int*)d_in[9];
    const int* pid = (const int*)d_in[10];
    const int* sid = (const int*)d_in[11];
    float* out = (float*)d_out;

    int K = in_sizes[0];                  // 1000
    int P = in_sizes[5];                  // 50000
    int B = in_sizes[8] / T_LEN;          // 8192 rows
    if (K > K_CAP) K = K_CAP;
    if (P > P_CAP) P = P_CAP;

    int n = (K > P) ? K : P;
    pack_tables<<<(n + 255) / 256, 256>>>(pT, pF, pG, pS, om, sg, K, P);

    int warps_per_block = THREADS / 32;
    int grid = (B + warps_per_block - 1) / warps_per_block;
    bkt_warp_scan<<<grid, THREADS>>>(pL0, ab, obs, kc, pid, sid, out, B);
}

// round 5
// speedup vs baseline: 1.8953x; 1.0074x over previous
#include <cuda_runtime.h>

// SuperchargingBKT — warp-per-row 2x2 projective matrix scan, round 4.
//
// R4 changes vs R3 (ncu: L1=68.9% top unit; occupancy raise gave ~0 -> kernel
// is l1tex-gather-throughput bound):
//  * KC logit table (1000 x float4 = 16KB) staged into shared memory per CTA;
//    per-step KC gather becomes LDS.128 (~4-8 crossbar phases) instead of an
//    LDG gather (~16-31 L1 wavefronts). ~1/3 of gather traffic removed.
//  * 64KB/CTA => dynamic shared memory (static limit is 48KB).
//
// Inputs (metadata order):
//  0 pL0_logit [K] f32   4 pS_logit [K] f32    8 observations [B,T] i32
//  1 pT_logit  [K] f32   5 omega    [P] f32    9 kc_ids       [B,T] i32
//  2 pF_logit  [K] f32   6 sigma    [P] f32   10 problem_ids  [B,T] i32
//  3 pG_logit  [K] f32   7 ability  [S,4] f32 11 student_ids  [B,T] i32
// Output: p_correct [B,T] f32

constexpr int T_LEN = 512;
constexpr int SEG   = 16;                 // steps per lane (32 lanes * 16 = 512)
constexpr int THREADS = 256;
constexpr int K_CAP = 1024;               // K = 1000
constexpr int P_CAP = 50048;              // P = 50000

constexpr int SMEM_KC_BYTES = K_CAP * 16;                     // 16KB
constexpr int SMEM_SC_BYTES = SEG * 3 * THREADS * 4;          // 48KB
constexpr int SMEM_TOTAL    = SMEM_KC_BYTES + SMEM_SC_BYTES;  // 64KB

__device__ float4 g_kcpack[K_CAP];        // (pT,pF,pG,pS) logits per KC
__device__ float2 g_pspack[P_CAP];        // (omega,sigma) per problem

__device__ __forceinline__ float sigmoidf(float x) {
    return __fdividef(1.0f, 1.0f + __expf(-x));
}

__global__ void pack_tables(
    const float* __restrict__ pT_logit, const float* __restrict__ pF_logit,
    const float* __restrict__ pG_logit, const float* __restrict__ pS_logit,
    const float* __restrict__ omega,    const float* __restrict__ sigma,
    int K, int P)
{
    int i = blockIdx.x * blockDim.x + threadIdx.x;
    if (i < K) {
        g_kcpack[i] = make_float4(pT_logit[i], pF_logit[i], pG_logit[i], pS_logit[i]);
    }
    if (i < P) {
        g_pspack[i] = make_float2(omega[i], sigma[i]);
    }
}

__global__ void __launch_bounds__(THREADS, 3)
bkt_warp_scan(
    const float* __restrict__ pL0_logit,
    const float4* __restrict__ ability,
    const int*  __restrict__ obs,
    const int*  __restrict__ kc,
    const int*  __restrict__ pid,
    const int*  __restrict__ sid,
    float* __restrict__ out,
    int B, int K)
{
    extern __shared__ char smem[];
    float4* kcTab = reinterpret_cast<float4*>(smem);                  // [K_CAP]
    float*  sC    = reinterpret_cast<float*>(smem + SMEM_KC_BYTES);   // [SEG][3][THREADS]

    const int tid  = threadIdx.x;
    const int lane = tid & 31;
    const int warp = (blockIdx.x * blockDim.x + tid) >> 5;

    // stage KC table into shared (coalesced)
    for (int i = tid; i < K; i += THREADS) kcTab[i] = g_kcpack[i];
    __syncthreads();

    if (warp >= B) return;

    const int base = warp * T_LEN;
    const int s0   = base + lane * SEG;    // this lane's first step

    float C4[SEG];
    unsigned obits = 0;

    // A maps segment-start state (hu,hm) -> state after processed steps.
    float a00 = 1.f, a01 = 0.f, a10 = 0.f, a11 = 1.f;

    // ---------------- pass 1: coefficients + segment matrix product --------
#pragma unroll
    for (int q = 0; q < SEG / 4; ++q) {
        const int o4i = s0 + 4 * q;
        int4 kv = *reinterpret_cast<const int4*>(kc  + o4i);
        int4 pv = *reinterpret_cast<const int4*>(pid + o4i);
        int4 sv = *reinterpret_cast<const int4*>(sid + o4i);
        int4 ov = *reinterpret_cast<const int4*>(obs + o4i);
        int kk[4] = {kv.x, kv.y, kv.z, kv.w};
        int pp[4] = {pv.x, pv.y, pv.z, pv.w};
        int ssx[4]= {sv.x, sv.y, sv.z, sv.w};
        int oo[4] = {ov.x, ov.y, ov.z, ov.w};

#pragma unroll
        for (int j = 0; j < 4; ++j) {
            const int i = 4 * q + j;
            float4 th  = __ldg(ability + ssx[j]);
            float4 kcp = kcTab[kk[j]];            // LDS.128 gather (smem)
            float2 psp = g_pspack[pp[j]];
            float pT = sigmoidf(kcp.x + th.x);
            float pF = sigmoidf(kcp.y - th.y);
            float pG = sigmoidf(kcp.z + psp.x + th.z);
            float pS = sigmoidf(kcp.w + psp.y - th.w);
            bool o = (oo[j] != 0);
            float pom = o ? (1.0f - pS) : pS;      // P(y | mastered)
            float pou = o ? pG : (1.0f - pG);      // P(y | unmastered)
            float c1 = (1.0f - pF) * pom;
            float c2 = pT * pou;
            float c3 = pF * pom;
            float c4 = (1.0f - pT) * pou;
            sC[(i * 3 + 0) * THREADS + tid] = c1;
            sC[(i * 3 + 1) * THREADS + tid] = c2;
            sC[(i * 3 + 2) * THREADS + tid] = c3;
            C4[i] = c4;
            obits |= (o ? 1u : 0u) << i;

            // A = M * A,  M = [[c4,c3],[c2,c1]]
            float n00 = fmaf(c4, a00, c3 * a10);
            float n01 = fmaf(c4, a01, c3 * a11);
            float n10 = fmaf(c2, a00, c1 * a10);
            float n11 = fmaf(c2, a01, c1 * a11);
            a00 = n00; a01 = n01; a10 = n10; a11 = n11;
        }
        if (q & 1) {
            // normalize every 8 steps (projective scale is irrelevant)
            float r = __fdividef(1.0f, a00 + a01 + a10 + a11);
            a00 *= r; a01 *= r; a10 *= r; a11 *= r;
        }
    }

    // ------------- inclusive warp scan of segment matrices -----------------
#pragma unroll
    for (int d = 1; d < 32; d <<= 1) {
        float b00 = __shfl_up_sync(0xFFFFFFFFu, a00, d);
        float b01 = __shfl_up_sync(0xFFFFFFFFu, a01, d);
        float b10 = __shfl_up_sync(0xFFFFFFFFu, a10, d);
        float b11 = __shfl_up_sync(0xFFFFFFFFu, a11, d);
        if (lane >= d) {
            float n00 = fmaf(a00, b00, a01 * b10);   // mine(later) * other(earlier)
            float n01 = fmaf(a00, b01, a01 * b11);
            float n10 = fmaf(a10, b00, a11 * b10);
            float n11 = fmaf(a10, b01, a11 * b11);
            float r = __fdividef(1.0f, n00 + n01 + n10 + n11);
            a00 = n00 * r; a01 = n01 * r; a10 = n10 * r; a11 = n11 * r;
        }
    }

    // exclusive prefix
    float e00 = __shfl_up_sync(0xFFFFFFFFu, a00, 1);
    float e01 = __shfl_up_sync(0xFFFFFFFFu, a01, 1);
    float e10 = __shfl_up_sync(0xFFFFFFFFu, a10, 1);
    float e11 = __shfl_up_sync(0xFFFFFFFFu, a11, 1);
    if (lane == 0) { e00 = 1.f; e01 = 0.f; e10 = 0.f; e11 = 1.f; }

    // initial state from pL0 at first KC (uniform broadcast load)
    float pL0 = sigmoidf(__ldg(pL0_logit + __ldg(kc + base)));
    float hu0 = 1.0f - pL0;
    float hm0 = pL0;
    float hu = fmaf(e00, hu0, e01 * hm0);
    float hm = fmaf(e10, hu0, e11 * hm0);
    float rs = __fdividef(1.0f, hu + hm);
    hu *= rs; hm *= rs;

    // ---------------- pass 2: replay segment, emit p_correct ---------------
    float* op = out + s0;
#pragma unroll
    for (int q = 0; q < SEG / 4; ++q) {
        float4 res;
        float* r4 = reinterpret_cast<float*>(&res);
#pragma unroll
        for (int j = 0; j < 4; ++j) {
            const int i = 4 * q + j;
            float c1 = sC[(i * 3 + 0) * THREADS + tid];
            float c2 = sC[(i * 3 + 1) * THREADS + tid];
            float c3 = sC[(i * 3 + 2) * THREADS + tid];
            float c4 = C4[i];
            float nm = fmaf(c1, hm, c2 * hu);
            float nu = fmaf(c3, hm, c4 * hu);
            float r  = __fdividef(1.0f, nm + nu);
            hm = nm * r;
            hu = nu * r;
            bool o = (obits >> i) & 1u;
            float pom = c1 + c3;                   // = 1-pS if o else pS
            float pou = c2 + c4;                   // = pG   if o else 1-pG
            float c5 = o ? pom : (1.0f - pom);     // 1-pS
            float c6 = o ? pou : (1.0f - pou);     // pG
            r4[j] = fmaf(c5, hm, c6 * hu);
        }
        *reinterpret_cast<float4*>(op + 4 * q) = res;
    }
}

extern "C" void kernel_launch(void* const* d_in, const int* in_sizes, int n_in,
                              void* d_out, int out_size) {
    const float* pL0 = (const float*)d_in[0];
    const float* pT  = (const float*)d_in[1];
    const float* pF  = (const float*)d_in[2];
    const float* pG  = (const float*)d_in[3];
    const float* pS  = (const float*)d_in[4];
    const float* om  = (const float*)d_in[5];
    const float* sg  = (const float*)d_in[6];
    const float4* ab = (const float4*)d_in[7];
    const int* obs = (const int*)d_in[8];
    const int* kc  = (const int*)d_in[9];
    const int* pid = (const int*)d_in[10];
    const int* sid = (const int*)d_in[11];
    float* out = (float*)d_out;

    int K = in_sizes[0];                  // 1000
    int P = in_sizes[5];                  // 50000
    int B = in_sizes[8] / T_LEN;          // 8192 rows
    if (K > K_CAP) K = K_CAP;
    if (P > P_CAP) P = P_CAP;

    // allow >48KB dynamic shared (attribute set is idempotent, not a stream op)
    cudaFuncSetAttribute(bkt_warp_scan,
                         cudaFuncAttributeMaxDynamicSharedMemorySize, SMEM_TOTAL);

    int n = (K > P) ? K : P;
    pack_tables<<<(n + 255) / 256, 256>>>(pT, pF, pG, pS, om, sg, K, P);

    int warps_per_block = THREADS / 32;
    int grid = (B + warps_per_block - 1) / warps_per_block;
    bkt_warp_scan<<<grid, THREADS, SMEM_TOTAL>>>(pL0, ab, obs, kc, pid, sid,
                                                 out, B, K);
}